// round 14
// baseline (speedup 1.0000x reference)
#include <cuda_runtime.h>
#include <cuda_fp16.h>
#include <cstdint>

#define CIN    64
#define COUT   64
#define KVOL   27
#define TILE_V 128
#define MAXN   120000
#define NBLK   ((MAXN + TILE_V - 1) / TILE_V)   // 938
#define NROWS  (NBLK * TILE_V)                   // 120064 padded rows
#define KOFF   26
#define PAIRCAP 8192
#define CHSZ   2048
#define NCH    ((MAXN + CHSZ - 1) / CHSZ)       // 59
#define STILE  64
#define NSLOT  (KOFF * STILE)                    // 1664

// padded A row: 144 B (72 halves); 144 mod 128 = 16 -> conflict-free ldmatrix
#define ROWB   144
#define ROWH   72

// conv smem: A @0 (18432), W @18432 (8192), dlist @26624 (512), mbar @27136
#define SP_W    18432
#define SP_DL   26624
#define SP_MB   27136
#define SP_SMEM 27200

// ---- device scratch (allocation-free) ----
__device__ __align__(16) float  g_out_raw[(size_t)MAXN * COUT];
__device__ __align__(16) __half g_fhp[(size_t)NROWS * ROWH];     // padded rows
__device__ __align__(16) __half g_whs[KVOL * CIN * COUT];        // pre-swizzled
__device__ __align__(16) __half g_zero[64];                      // zero row
__device__ int   g_psrc[KOFF * PAIRCAP];
__device__ int   g_pdst[KOFF * PAIRCAP];
__device__ int   g_mcount[KOFF];
__device__ int   g_pscount;
__device__ float g_partial[(size_t)NBLK * 2 * COUT];
__device__ float g_scale[COUT];
__device__ float g_bias[COUT];

// --------------------------- PTX helpers -----------------------------------
__device__ __forceinline__ uint32_t smem_u32(const void* p) {
    return (uint32_t)__cvta_generic_to_shared(p);
}
__device__ __forceinline__ void bulkcp(uint32_t dst, const void* src,
                                       uint32_t bytes, uint32_t mbar) {
    asm volatile("cp.async.bulk.shared::cta.global.mbarrier::complete_tx::bytes "
                 "[%0], [%1], %2, [%3];"
                 :: "r"(dst), "l"(src), "r"(bytes), "r"(mbar) : "memory");
}
__device__ __forceinline__ void mbar_init(uint32_t a, uint32_t cnt) {
    asm volatile("mbarrier.init.shared.b64 [%0], %1;" :: "r"(a), "r"(cnt) : "memory");
}
__device__ __forceinline__ void mbar_expect(uint32_t a, uint32_t bytes) {
    asm volatile("mbarrier.arrive.expect_tx.shared.b64 _, [%0], %1;"
                 :: "r"(a), "r"(bytes) : "memory");
}
__device__ __forceinline__ void mbar_wait(uint32_t a, uint32_t parity) {
    uint32_t done;
    asm volatile("{\n\t.reg .pred p;\n\t"
                 "mbarrier.try_wait.parity.acquire.cta.shared::cta.b64 p, [%1], %2;\n\t"
                 "selp.b32 %0, 1, 0, p;\n\t}"
                 : "=r"(done) : "r"(a), "r"(parity) : "memory");
    if (!done) {
        asm volatile("{\n\t.reg .pred P1;\n\t"
                     "WL_%=:\n\t"
                     "mbarrier.try_wait.parity.acquire.cta.shared::cta.b64 P1, [%0], %1, 0x989680;\n\t"
                     "@P1 bra.uni WD_%=;\n\t"
                     "bra.uni WL_%=;\n\t"
                     "WD_%=:\n\t}" :: "r"(a), "r"(parity) : "memory");
    }
}
__device__ __forceinline__ void ldmx4(uint32_t& r0, uint32_t& r1, uint32_t& r2,
                                      uint32_t& r3, uint32_t a) {
    asm volatile("ldmatrix.sync.aligned.m8n8.x4.shared.b16 {%0,%1,%2,%3}, [%4];"
                 : "=r"(r0), "=r"(r1), "=r"(r2), "=r"(r3) : "r"(a));
}
__device__ __forceinline__ void ldmx4t(uint32_t& r0, uint32_t& r1, uint32_t& r2,
                                       uint32_t& r3, uint32_t a) {
    asm volatile("ldmatrix.sync.aligned.m8n8.x4.trans.shared.b16 {%0,%1,%2,%3}, [%4];"
                 : "=r"(r0), "=r"(r1), "=r"(r2), "=r"(r3) : "r"(a));
}
__device__ __forceinline__ void mma16816(float* c, const uint32_t* a,
                                         const uint32_t* b) {
    asm volatile(
        "mma.sync.aligned.m16n8k16.row.col.f32.f16.f16.f32 "
        "{%0,%1,%2,%3}, {%4,%5,%6,%7}, {%8,%9}, {%0,%1,%2,%3};"
        : "+f"(c[0]), "+f"(c[1]), "+f"(c[2]), "+f"(c[3])
        : "r"(a[0]), "r"(a[1]), "r"(a[2]), "r"(a[3]), "r"(b[0]), "r"(b[1]));
}
__device__ __forceinline__ void redadd4(float* p, float a, float b,
                                        float c, float d) {
    asm volatile("red.global.add.v4.f32 [%0], {%1, %2, %3, %4};"
                 :: "l"(p), "f"(a), "f"(b), "f"(c), "f"(d) : "memory");
}

// --------------------------- convert + zero prologue ------------------------
// sections: [0,nf): feats->padded fp16; [nf,nf+w): weight->swizzled fp16;
// [nf+w, nf+w+z): zero g_out_raw. Block 0 also resets counters.
__global__ __launch_bounds__(256) void convert_kernel(
    const float* __restrict__ feats, const float* __restrict__ weight,
    int total4, int nf_blocks, int w_blocks, int zero4)
{
    if (blockIdx.x == 0 && threadIdx.x < KOFF + 1) {
        if (threadIdx.x < KOFF) g_mcount[threadIdx.x] = 0;
        else g_pscount = 0;
    }
    if ((int)blockIdx.x < nf_blocks) {
        int idx = blockIdx.x * 256 + threadIdx.x;
        if (idx >= total4) return;
        float4 x = ((const float4*)feats)[idx];
        const int row = idx >> 4, c4 = idx & 15;
        __half2* ph = (__half2*)g_fhp;
        const size_t o = (size_t)row * (ROWH / 2) + c4 * 2;
        ph[o]     = __floats2half2_rn(x.x, x.y);
        ph[o + 1] = __floats2half2_rn(x.z, x.w);
    } else if ((int)blockIdx.x < nf_blocks + w_blocks) {
        int idx = (blockIdx.x - nf_blocks) * 256 + threadIdx.x;   // half2 index
        if (idx * 2 >= KVOL * CIN * COUT) return;
        float2 w = ((const float2*)weight)[idx];
        const int k = idx / 2048, i = idx % 2048;
        const int b = i * 4;
        const int r = b >> 7, c = (b >> 4) & 7, rem = b & 15;
        const int swz = r * 128 + ((c ^ (r & 7)) << 4) + rem;
        ((__half2*)g_whs)[(k * 8192 + swz) >> 2] = __floats2half2_rn(w.x, w.y);
    } else {
        int idx = (blockIdx.x - nf_blocks - w_blocks) * 256 + threadIdx.x;
        if (idx < zero4)
            ((float4*)g_out_raw)[idx] = make_float4(0.f, 0.f, 0.f, 0.f);
    }
}

// --------------------------- warp-autonomous compaction ---------------------
__global__ __launch_bounds__(256) void fill_kernel(
    const int* __restrict__ nbr, int n)
{
    const int kk = blockIdx.x / NCH;
    const int ch = blockIdx.x % NCH;
    const int k  = (kk < 13) ? kk : kk + 1;
    const int tid  = threadIdx.x;
    const int lane = tid & 31;
    const int idx0 = ch * CHSZ + tid * 8;

    int v[8];
    if (idx0 + 7 < n) {
        const int4* p = (const int4*)(nbr + (size_t)k * n + idx0);
        int4 x0 = __ldg(p);
        int4 x1 = __ldg(p + 1);
        v[0] = x0.x; v[1] = x0.y; v[2] = x0.z; v[3] = x0.w;
        v[4] = x1.x; v[5] = x1.y; v[6] = x1.z; v[7] = x1.w;
    } else {
#pragma unroll
        for (int j = 0; j < 8; ++j) {
            const int idx = idx0 + j;
            v[j] = (idx < n) ? __ldg(nbr + (size_t)k * n + idx) : -1;
        }
    }
    int tc = 0;
#pragma unroll
    for (int j = 0; j < 8; ++j)
        if (v[j] >= 0) ++tc;

    int sc = tc;
#pragma unroll
    for (int off = 1; off < 32; off <<= 1) {
        int t = __shfl_up_sync(0xFFFFFFFFu, sc, off);
        if (lane >= off) sc += t;
    }
    int wb = 0;
    if (lane == 31) wb = atomicAdd(&g_mcount[kk], sc);
    wb = __shfl_sync(0xFFFFFFFFu, wb, 31);

    int pos = wb + sc - tc;
#pragma unroll
    for (int j = 0; j < 8; ++j) {
        if (v[j] >= 0) {
            if (pos < PAIRCAP) {
                g_psrc[kk * PAIRCAP + pos] = v[j];
                g_pdst[kk * PAIRCAP + pos] = idx0 + j;
            }
            ++pos;
        }
    }
}

// --------------------------- unified conv kernel ----------------------------
// grid = NSLOT + NBLK. bid < NSLOT: sparse offset tile (gathered A rows, RED
// scatter via pair list). bid >= NSLOT: center tile (sequential rows, k=13,
// RED scatter to own rows). All blocks RED into zeroed g_out_raw: order-free.
__global__ __launch_bounds__(128) void conv_kernel(int n)
{
    extern __shared__ char smem[];
    const uint32_t sb = smem_u32(smem);
    const int* dlist = (const int*)(smem + SP_DL);
    const int tid  = threadIdx.x;
    const int wid  = tid >> 5;
    const int lane = tid & 31;
    const int warp_m = wid >> 1;
    const int warp_n = wid & 1;
    const int l15   = lane & 15;
    const int lhalf = lane >> 4;

    const bool is_center = (int)blockIdx.x >= NSLOT;
    int m0 = 0, Mk = 0, kk = 0, v0 = 0;

    if (is_center) {
        v0 = ((int)blockIdx.x - NSLOT) * TILE_V;
    } else {
        kk = blockIdx.x / STILE;
        const int t = blockIdx.x % STILE;
        Mk = __ldg(&g_mcount[kk]);
        if (Mk > PAIRCAP) Mk = PAIRCAP;
        m0 = t * TILE_V;
        if (m0 >= Mk) return;
    }

    if (tid == 0) mbar_init(sb + SP_MB, 1);
    __syncthreads();

    if (is_center) {
        if (tid == 0) {
            mbar_expect(sb + SP_MB, 18432 + 8192);
            bulkcp(sb, g_fhp + (size_t)v0 * ROWH, 18432, sb + SP_MB);
            bulkcp(sb + SP_W, g_whs + 13 * 4096, 8192, sb + SP_MB);
        }
    } else {
        if (tid == 0)
            mbar_expect(sb + SP_MB, 16384 + 8192 + 512);
        const bool valid = (m0 + tid) < Mk;
        const int src = valid ? __ldg(g_psrc + kk * PAIRCAP + m0 + tid) : 0;
        const __half* sp = valid ? (g_fhp + (size_t)src * ROWH) : g_zero;
        bulkcp(sb + (uint32_t)tid * ROWB, sp, 128, sb + SP_MB);
        if (tid == 0) {
            const int k = (kk < 13) ? kk : kk + 1;
            bulkcp(sb + SP_W, g_whs + k * 4096, 8192, sb + SP_MB);
            bulkcp(sb + SP_DL, g_pdst + kk * PAIRCAP + m0, 512, sb + SP_MB);
        }
    }
    mbar_wait(sb + SP_MB, 0);

    float acc[4][4][4];
#pragma unroll
    for (int mi = 0; mi < 4; ++mi)
#pragma unroll
        for (int ni = 0; ni < 4; ++ni)
#pragma unroll
            for (int r = 0; r < 4; ++r) acc[mi][ni][r] = 0.f;

    const uint32_t arow = (uint32_t)(warp_m * 64 + l15);
    const uint32_t bkrow = (uint32_t)l15;
    const uint32_t bxor  = (uint32_t)(l15 & 7);

#pragma unroll
    for (int ks = 0; ks < 4; ++ks) {
        uint32_t bfrag[4][2];
#pragma unroll
        for (int p = 0; p < 2; ++p) {
            const uint32_t kk2 = bkrow + ks * 16;
            const uint32_t ch = (uint32_t)(warp_n * 4 + 2 * p + lhalf);
            const uint32_t ad = sb + SP_W + kk2 * 128 + ((ch ^ bxor) << 4);
            ldmx4t(bfrag[2 * p][0], bfrag[2 * p][1],
                   bfrag[2 * p + 1][0], bfrag[2 * p + 1][1], ad);
        }
#pragma unroll
        for (int mi = 0; mi < 4; ++mi) {
            const uint32_t row = arow + mi * 16;
            const uint32_t ch  = (uint32_t)(ks * 2 + lhalf);
            const uint32_t ad  = sb + row * ROWB + (ch << 4);
            uint32_t afrag[4];
            ldmx4(afrag[0], afrag[1], afrag[2], afrag[3], ad);
#pragma unroll
            for (int ni = 0; ni < 4; ++ni)
                mma16816(acc[mi][ni], afrag, bfrag[ni]);
        }
    }

    // RED scatter (v4 via shfl pairing). Center: dst = v0 + row (bounds vs n);
    // sparse: dst from dlist (bounds vs Mk).
    const int rloc = warp_m * 64 + (lane >> 2);
    const int cq = warp_n * 32 + (lane & 3) * 2;
#pragma unroll
    for (int mi = 0; mi < 4; ++mi) {
        const int r0 = rloc + mi * 16;
        const int r1 = r0 + 8;
        int d0, d1;
        if (is_center) {
            d0 = (v0 + r0 < n) ? v0 + r0 : -1;
            d1 = (v0 + r1 < n) ? v0 + r1 : -1;
        } else {
            d0 = (m0 + r0 < Mk) ? dlist[r0] : -1;
            d1 = (m0 + r1 < Mk) ? dlist[r1] : -1;
        }
#pragma unroll
        for (int ni = 0; ni < 4; ++ni) {
            float a0 = acc[mi][ni][0], a1 = acc[mi][ni][1];
            float a2 = acc[mi][ni][2], a3 = acc[mi][ni][3];
            float p0 = __shfl_xor_sync(0xFFFFFFFFu, a0, 1);
            float p1 = __shfl_xor_sync(0xFFFFFFFFu, a1, 1);
            float p2 = __shfl_xor_sync(0xFFFFFFFFu, a2, 1);
            float p3 = __shfl_xor_sync(0xFFFFFFFFu, a3, 1);
            if (!(lane & 1)) {
                const int cc = cq + ni * 8;
                if (d0 >= 0)
                    redadd4(g_out_raw + (size_t)d0 * COUT + cc, a0, a1, p0, p1);
                if (d1 >= 0)
                    redadd4(g_out_raw + (size_t)d1 * COUT + cc, a2, a3, p2, p3);
            }
        }
    }
}

// --------------------------- BN partials + fused stats -----------------------
__global__ __launch_bounds__(256) void partial_stats_kernel(
    const float* __restrict__ gamma, const float* __restrict__ beta,
    int n, int nblk)
{
    __shared__ float ss[4][64], sq[4][64];
    const int b = blockIdx.x, tdx = threadIdx.x;
    const int c = tdx & 63, g = tdx >> 6;
    const int r0 = b * TILE_V;
    const int r1 = min(n, r0 + TILE_V);
    float s = 0.f, q = 0.f;
    for (int r = r0 + g; r < r1; r += 4) {
        float v = g_out_raw[(size_t)r * COUT + c];
        s += v; q += v * v;
    }
    ss[g][c] = s; sq[g][c] = q;
    __syncthreads();
    if (tdx < 64) {
        g_partial[(size_t)b * 128 + tdx]      = ss[0][tdx] + ss[1][tdx] + ss[2][tdx] + ss[3][tdx];
        g_partial[(size_t)b * 128 + 64 + tdx] = sq[0][tdx] + sq[1][tdx] + sq[2][tdx] + sq[3][tdx];
    }

    // last-block reduces all partials (deterministic: fixed order, fixed data)
    __threadfence();
    __shared__ int is_last;
    if (tdx == 0) is_last = (atomicAdd(&g_pscount, 1) == nblk - 1) ? 1 : 0;
    __syncthreads();
    if (!is_last) return;

    __shared__ float red[2][128];
    __shared__ double dd[128];
    const int cc = tdx & 127;
    const int gg = tdx >> 7;   // 0..1
    float a = 0.f;
    for (int bb = gg; bb < nblk; bb += 2)
        a += g_partial[(size_t)bb * 128 + cc];
    red[gg][cc] = a;
    __syncthreads();
    if (tdx < 128)
        dd[tdx] = (double)red[0][tdx] + (double)red[1][tdx];
    __syncthreads();
    if (tdx < 64) {
        const double mean = dd[tdx] / (double)n;
        const double var  = dd[64 + tdx] / (double)n - mean * mean;
        const double inv  = rsqrt(var + 1e-5);
        g_scale[tdx] = (float)((double)gamma[tdx] * inv);
        g_bias[tdx]  = (float)((double)beta[tdx] - mean * (double)gamma[tdx] * inv);
    }
}

// --------------------------- normalize + ReLU -------------------------------
__global__ __launch_bounds__(256) void bnrelu_kernel(float* __restrict__ out, int n)
{
    const int g = blockIdx.x * 256 + threadIdx.x;
    const int slot = g & 15;
    const int d0 = slot << 2;
    const float s0 = g_scale[d0],     s1 = g_scale[d0 + 1];
    const float s2 = g_scale[d0 + 2], s3 = g_scale[d0 + 3];
    const float b0 = g_bias[d0],      b1 = g_bias[d0 + 1];
    const float b2 = g_bias[d0 + 2],  b3 = g_bias[d0 + 3];
    const int rstride = (gridDim.x * 256) >> 4;
    for (int r = g >> 4; r < n; r += rstride) {
        const int i = r * 16 + slot;
        float4 x = ((const float4*)g_out_raw)[i];
        float4 y;
        y.x = fmaxf(fmaf(x.x, s0, b0), 0.f);
        y.y = fmaxf(fmaf(x.y, s1, b1), 0.f);
        y.z = fmaxf(fmaf(x.z, s2, b2), 0.f);
        y.w = fmaxf(fmaf(x.w, s3, b3), 0.f);
        ((float4*)out)[i] = y;
    }
}

// ---------------------------------------------------------------------------
extern "C" void kernel_launch(void* const* d_in, const int* in_sizes, int n_in,
                              void* d_out, int out_size)
{
    const float* feats  = (const float*)d_in[0];   // [N, 64]
    const float* weight = (const float*)d_in[1];   // [27, 64, 64]
    const float* gamma  = (const float*)d_in[2];   // [64]
    const float* beta   = (const float*)d_in[3];   // [64]
    const int*   nbr    = (const int*)d_in[4];     // [27, N]

    int n = in_sizes[0] / CIN;
    if (n > MAXN) n = MAXN;
    const int nblk = (n + TILE_V - 1) / TILE_V;

    static bool attr_set = false;
    if (!attr_set) {
        cudaFuncSetAttribute(conv_kernel,
                             cudaFuncAttributeMaxDynamicSharedMemorySize, SP_SMEM);
        attr_set = true;
    }

    const int total4 = n * CIN / 4;
    const int nf_blocks = (total4 + 255) / 256;
    const int w_blocks  = (KVOL * CIN * COUT / 2 + 255) / 256;
    const int zero4     = n * (COUT / 4);
    const int z_blocks  = (zero4 + 255) / 256;
    convert_kernel<<<nf_blocks + w_blocks + z_blocks, 256>>>(
        feats, weight, total4, nf_blocks, w_blocks, zero4);

    fill_kernel<<<KOFF * NCH, 256>>>(nbr, n);

    conv_kernel<<<NSLOT + nblk, 128, SP_SMEM>>>(n);

    partial_stats_kernel<<<nblk, 256>>>(gamma, beta, n, nblk);

    bnrelu_kernel<<<960, 256>>>((float*)d_out, n);
}

// round 15
// speedup vs baseline: 1.1366x; 1.1366x over previous
#include <cuda_runtime.h>
#include <cuda_fp16.h>
#include <cstdint>

#define CIN    64
#define COUT   64
#define KVOL   27
#define TILE_V 128
#define MAXN   120000
#define NBLK   ((MAXN + TILE_V - 1) / TILE_V)   // 938
#define NROWS  (NBLK * TILE_V)                   // 120064 padded rows
#define KOFF   26
#define PAIRCAP 8192
#define CHSZ   2048
#define NCH    ((MAXN + CHSZ - 1) / CHSZ)       // 59
#define STILE  64
#define NSLOT  (KOFF * STILE)                    // 1664

// padded A row: 144 B (72 halves); 144 mod 128 = 16 -> conflict-free ldmatrix
#define ROWB   144
#define ROWH   72

// sparse smem: A @0 (18432), W @18432 (8192), dlist @26624 (512), mbar @27136
#define SP_W    18432
#define SP_DL   26624
#define SP_MB   27136
#define SP_SMEM 27200
// center smem: A @0 (18432), W @18432 (8192), mbar @26624
#define CT_MB   26624
#define CT_SMEM 26688

// ---- device scratch (allocation-free) ----
__device__ __align__(16) float  g_out_raw[(size_t)MAXN * COUT];
__device__ __align__(16) __half g_fhp[(size_t)NROWS * ROWH];     // padded rows
__device__ __align__(16) __half g_whs[KVOL * CIN * COUT];        // pre-swizzled
__device__ __align__(16) __half g_zero[64];                      // zero row
__device__ int   g_psrc[KOFF * PAIRCAP];
__device__ int   g_pdst[KOFF * PAIRCAP];
__device__ int   g_mcount[KOFF];
__device__ float g_partial[(size_t)NBLK * 2 * COUT];
__device__ float g_scale[COUT];
__device__ float g_bias[COUT];

// --------------------------- PTX helpers -----------------------------------
__device__ __forceinline__ uint32_t smem_u32(const void* p) {
    return (uint32_t)__cvta_generic_to_shared(p);
}
__device__ __forceinline__ void bulkcp(uint32_t dst, const void* src,
                                       uint32_t bytes, uint32_t mbar) {
    asm volatile("cp.async.bulk.shared::cta.global.mbarrier::complete_tx::bytes "
                 "[%0], [%1], %2, [%3];"
                 :: "r"(dst), "l"(src), "r"(bytes), "r"(mbar) : "memory");
}
__device__ __forceinline__ void mbar_init(uint32_t a, uint32_t cnt) {
    asm volatile("mbarrier.init.shared.b64 [%0], %1;" :: "r"(a), "r"(cnt) : "memory");
}
__device__ __forceinline__ void mbar_expect(uint32_t a, uint32_t bytes) {
    asm volatile("mbarrier.arrive.expect_tx.shared.b64 _, [%0], %1;"
                 :: "r"(a), "r"(bytes) : "memory");
}
__device__ __forceinline__ void mbar_wait(uint32_t a, uint32_t parity) {
    uint32_t done;
    asm volatile("{\n\t.reg .pred p;\n\t"
                 "mbarrier.try_wait.parity.acquire.cta.shared::cta.b64 p, [%1], %2;\n\t"
                 "selp.b32 %0, 1, 0, p;\n\t}"
                 : "=r"(done) : "r"(a), "r"(parity) : "memory");
    if (!done) {
        asm volatile("{\n\t.reg .pred P1;\n\t"
                     "WL_%=:\n\t"
                     "mbarrier.try_wait.parity.acquire.cta.shared::cta.b64 P1, [%0], %1, 0x989680;\n\t"
                     "@P1 bra.uni WD_%=;\n\t"
                     "bra.uni WL_%=;\n\t"
                     "WD_%=:\n\t}" :: "r"(a), "r"(parity) : "memory");
    }
}
__device__ __forceinline__ void ldmx4(uint32_t& r0, uint32_t& r1, uint32_t& r2,
                                      uint32_t& r3, uint32_t a) {
    asm volatile("ldmatrix.sync.aligned.m8n8.x4.shared.b16 {%0,%1,%2,%3}, [%4];"
                 : "=r"(r0), "=r"(r1), "=r"(r2), "=r"(r3) : "r"(a));
}
__device__ __forceinline__ void ldmx4t(uint32_t& r0, uint32_t& r1, uint32_t& r2,
                                       uint32_t& r3, uint32_t a) {
    asm volatile("ldmatrix.sync.aligned.m8n8.x4.trans.shared.b16 {%0,%1,%2,%3}, [%4];"
                 : "=r"(r0), "=r"(r1), "=r"(r2), "=r"(r3) : "r"(a));
}
__device__ __forceinline__ void mma16816(float* c, const uint32_t* a,
                                         const uint32_t* b) {
    asm volatile(
        "mma.sync.aligned.m16n8k16.row.col.f32.f16.f16.f32 "
        "{%0,%1,%2,%3}, {%4,%5,%6,%7}, {%8,%9}, {%0,%1,%2,%3};"
        : "+f"(c[0]), "+f"(c[1]), "+f"(c[2]), "+f"(c[3])
        : "r"(a[0]), "r"(a[1]), "r"(a[2]), "r"(a[3]), "r"(b[0]), "r"(b[1]));
}
__device__ __forceinline__ void redadd4(float* p, float a, float b,
                                        float c, float d) {
    asm volatile("red.global.add.v4.f32 [%0], {%1, %2, %3, %4};"
                 :: "l"(p), "f"(a), "f"(b), "f"(c), "f"(d) : "memory");
}

// --------------------------- convert prologue ------------------------------
__global__ __launch_bounds__(256) void convert_kernel(
    const float* __restrict__ feats, const float* __restrict__ weight,
    int total4, int nf_blocks)
{
    if (blockIdx.x == 0 && threadIdx.x < KOFF) g_mcount[threadIdx.x] = 0;
    if ((int)blockIdx.x < nf_blocks) {
        int idx = blockIdx.x * 256 + threadIdx.x;
        if (idx >= total4) return;
        float4 x = ((const float4*)feats)[idx];
        const int row = idx >> 4, c4 = idx & 15;
        __half2* ph = (__half2*)g_fhp;
        const size_t o = (size_t)row * (ROWH / 2) + c4 * 2;
        ph[o]     = __floats2half2_rn(x.x, x.y);
        ph[o + 1] = __floats2half2_rn(x.z, x.w);
    } else {
        int idx = (blockIdx.x - nf_blocks) * 256 + threadIdx.x;   // half2 index
        if (idx * 2 >= KVOL * CIN * COUT) return;
        float2 w = ((const float2*)weight)[idx];
        const int k = idx / 2048, i = idx % 2048;
        const int b = i * 4;
        const int r = b >> 7, c = (b >> 4) & 7, rem = b & 15;
        const int swz = r * 128 + ((c ^ (r & 7)) << 4) + rem;
        ((__half2*)g_whs)[(k * 8192 + swz) >> 2] = __floats2half2_rn(w.x, w.y);
    }
}

// --------------------------- warp-autonomous compaction ---------------------
__global__ __launch_bounds__(256) void fill_kernel(
    const int* __restrict__ nbr, int n)
{
    const int kk = blockIdx.x / NCH;
    const int ch = blockIdx.x % NCH;
    const int k  = (kk < 13) ? kk : kk + 1;
    const int tid  = threadIdx.x;
    const int lane = tid & 31;
    const int idx0 = ch * CHSZ + tid * 8;

    int v[8];
    if (idx0 + 7 < n) {
        const int4* p = (const int4*)(nbr + (size_t)k * n + idx0);
        int4 x0 = __ldg(p);
        int4 x1 = __ldg(p + 1);
        v[0] = x0.x; v[1] = x0.y; v[2] = x0.z; v[3] = x0.w;
        v[4] = x1.x; v[5] = x1.y; v[6] = x1.z; v[7] = x1.w;
    } else {
#pragma unroll
        for (int j = 0; j < 8; ++j) {
            const int idx = idx0 + j;
            v[j] = (idx < n) ? __ldg(nbr + (size_t)k * n + idx) : -1;
        }
    }
    int tc = 0;
#pragma unroll
    for (int j = 0; j < 8; ++j)
        if (v[j] >= 0) ++tc;

    int sc = tc;
#pragma unroll
    for (int off = 1; off < 32; off <<= 1) {
        int t = __shfl_up_sync(0xFFFFFFFFu, sc, off);
        if (lane >= off) sc += t;
    }
    int wb = 0;
    if (lane == 31) wb = atomicAdd(&g_mcount[kk], sc);
    wb = __shfl_sync(0xFFFFFFFFu, wb, 31);

    int pos = wb + sc - tc;
#pragma unroll
    for (int j = 0; j < 8; ++j) {
        if (v[j] >= 0) {
            if (pos < PAIRCAP) {
                g_psrc[kk * PAIRCAP + pos] = v[j];
                g_pdst[kk * PAIRCAP + pos] = idx0 + j;
            }
            ++pos;
        }
    }
}

// --------------------------- center GEMM (k=13, dense write) ----------------
__global__ __launch_bounds__(128) void center_kernel(int n)
{
    extern __shared__ char smem[];
    const uint32_t sb = smem_u32(smem);
    const int tid  = threadIdx.x;
    const int wid  = tid >> 5;
    const int lane = tid & 31;
    const int warp_m = wid >> 1;
    const int warp_n = wid & 1;
    const int v0 = blockIdx.x * TILE_V;

    const int l15   = lane & 15;
    const int lhalf = lane >> 4;

    if (tid == 0) mbar_init(sb + CT_MB, 1);
    __syncthreads();
    if (tid == 0) {
        mbar_expect(sb + CT_MB, 18432 + 8192);
        bulkcp(sb, g_fhp + (size_t)v0 * ROWH, 18432, sb + CT_MB);
        bulkcp(sb + SP_W, g_whs + 13 * 4096, 8192, sb + CT_MB);
    }
    mbar_wait(sb + CT_MB, 0);

    float acc[4][4][4];
#pragma unroll
    for (int mi = 0; mi < 4; ++mi)
#pragma unroll
        for (int ni = 0; ni < 4; ++ni)
#pragma unroll
            for (int r = 0; r < 4; ++r) acc[mi][ni][r] = 0.f;

    const uint32_t arow = (uint32_t)(warp_m * 64 + l15);
    const uint32_t bkrow = (uint32_t)l15;
    const uint32_t bxor  = (uint32_t)(l15 & 7);

#pragma unroll
    for (int ks = 0; ks < 4; ++ks) {
        uint32_t bfrag[4][2];
#pragma unroll
        for (int p = 0; p < 2; ++p) {
            const uint32_t kk2 = bkrow + ks * 16;
            const uint32_t ch = (uint32_t)(warp_n * 4 + 2 * p + lhalf);
            const uint32_t ad = sb + SP_W + kk2 * 128 + ((ch ^ bxor) << 4);
            ldmx4t(bfrag[2 * p][0], bfrag[2 * p][1],
                   bfrag[2 * p + 1][0], bfrag[2 * p + 1][1], ad);
        }
#pragma unroll
        for (int mi = 0; mi < 4; ++mi) {
            const uint32_t row = arow + mi * 16;
            const uint32_t ch  = (uint32_t)(ks * 2 + lhalf);
            const uint32_t ad  = sb + row * ROWB + (ch << 4);
            uint32_t afrag[4];
            ldmx4(afrag[0], afrag[1], afrag[2], afrag[3], ad);
#pragma unroll
            for (int ni = 0; ni < 4; ++ni)
                mma16816(acc[mi][ni], afrag, bfrag[ni]);
        }
    }

    const int rbase = v0 + warp_m * 64 + (lane >> 2);
    const int cbase = warp_n * 32 + (lane & 3) * 2;
#pragma unroll
    for (int mi = 0; mi < 4; ++mi) {
#pragma unroll
        for (int ni = 0; ni < 4; ++ni) {
            const int r0 = rbase + mi * 16;
            const int cc = cbase + ni * 8;
            if (r0 < n)
                *(float2*)(g_out_raw + (size_t)r0 * COUT + cc) =
                    make_float2(acc[mi][ni][0], acc[mi][ni][1]);
            if (r0 + 8 < n)
                *(float2*)(g_out_raw + (size_t)(r0 + 8) * COUT + cc) =
                    make_float2(acc[mi][ni][2], acc[mi][ni][3]);
        }
    }
}

// --------------------------- sparse GEMM + v4 scatter ------------------------
__global__ __launch_bounds__(128) void sparse_kernel(int n)
{
    const int kk = blockIdx.x / STILE;
    const int t  = blockIdx.x % STILE;
    int Mk = __ldg(&g_mcount[kk]);
    if (Mk > PAIRCAP) Mk = PAIRCAP;
    const int m0 = t * TILE_V;
    if (m0 >= Mk) return;

    extern __shared__ char smem[];
    const uint32_t sb = smem_u32(smem);
    const int* dlist = (const int*)(smem + SP_DL);
    const int tid  = threadIdx.x;
    const int wid  = tid >> 5;
    const int lane = tid & 31;
    const int warp_m = wid >> 1;
    const int warp_n = wid & 1;

    const int l15   = lane & 15;
    const int lhalf = lane >> 4;

    if (tid == 0) mbar_init(sb + SP_MB, 1);
    __syncthreads();
    if (tid == 0)
        mbar_expect(sb + SP_MB, 16384 + 8192 + 512);

    {
        const bool valid = (m0 + tid) < Mk;
        const int src = valid ? __ldg(g_psrc + kk * PAIRCAP + m0 + tid) : 0;
        const __half* sp = valid ? (g_fhp + (size_t)src * ROWH) : g_zero;
        bulkcp(sb + (uint32_t)tid * ROWB, sp, 128, sb + SP_MB);
    }
    if (tid == 0) {
        const int k = (kk < 13) ? kk : kk + 1;
        bulkcp(sb + SP_W, g_whs + k * 4096, 8192, sb + SP_MB);
        bulkcp(sb + SP_DL, g_pdst + kk * PAIRCAP + m0, 512, sb + SP_MB);
    }
    mbar_wait(sb + SP_MB, 0);

    float acc[4][4][4];
#pragma unroll
    for (int mi = 0; mi < 4; ++mi)
#pragma unroll
        for (int ni = 0; ni < 4; ++ni)
#pragma unroll
            for (int r = 0; r < 4; ++r) acc[mi][ni][r] = 0.f;

    const uint32_t arow = (uint32_t)(warp_m * 64 + l15);
    const uint32_t bkrow = (uint32_t)l15;
    const uint32_t bxor  = (uint32_t)(l15 & 7);

#pragma unroll
    for (int ks = 0; ks < 4; ++ks) {
        uint32_t bfrag[4][2];
#pragma unroll
        for (int p = 0; p < 2; ++p) {
            const uint32_t kk2 = bkrow + ks * 16;
            const uint32_t ch = (uint32_t)(warp_n * 4 + 2 * p + lhalf);
            const uint32_t ad = sb + SP_W + kk2 * 128 + ((ch ^ bxor) << 4);
            ldmx4t(bfrag[2 * p][0], bfrag[2 * p][1],
                   bfrag[2 * p + 1][0], bfrag[2 * p + 1][1], ad);
        }
#pragma unroll
        for (int mi = 0; mi < 4; ++mi) {
            const uint32_t row = arow + mi * 16;
            const uint32_t ch  = (uint32_t)(ks * 2 + lhalf);
            const uint32_t ad  = sb + row * ROWB + (ch << 4);
            uint32_t afrag[4];
            ldmx4(afrag[0], afrag[1], afrag[2], afrag[3], ad);
#pragma unroll
            for (int ni = 0; ni < 4; ++ni)
                mma16816(acc[mi][ni], afrag, bfrag[ni]);
        }
    }

    const int rloc = warp_m * 64 + (lane >> 2);
    const int cq = warp_n * 32 + (lane & 3) * 2;
#pragma unroll
    for (int mi = 0; mi < 4; ++mi) {
        const int r0 = rloc + mi * 16;
        const int r1 = r0 + 8;
        const int d0 = (m0 + r0 < Mk) ? dlist[r0] : -1;
        const int d1 = (m0 + r1 < Mk) ? dlist[r1] : -1;
#pragma unroll
        for (int ni = 0; ni < 4; ++ni) {
            float a0 = acc[mi][ni][0], a1 = acc[mi][ni][1];
            float a2 = acc[mi][ni][2], a3 = acc[mi][ni][3];
            float p0 = __shfl_xor_sync(0xFFFFFFFFu, a0, 1);
            float p1 = __shfl_xor_sync(0xFFFFFFFFu, a1, 1);
            float p2 = __shfl_xor_sync(0xFFFFFFFFu, a2, 1);
            float p3 = __shfl_xor_sync(0xFFFFFFFFu, a3, 1);
            if (!(lane & 1)) {
                const int cc = cq + ni * 8;
                if (d0 >= 0)
                    redadd4(g_out_raw + (size_t)d0 * COUT + cc, a0, a1, p0, p1);
                if (d1 >= 0)
                    redadd4(g_out_raw + (size_t)d1 * COUT + cc, a2, a3, p2, p3);
            }
        }
    }
}

// --------------------------- BN partials (coalesced float4) ------------------
// Thread slot = tid&15 owns channel quad slot*4..+3; rgrp = tid>>4 covers rows
// r0+rgrp, step 16 (8 iters for 128 rows). Fully coalesced float4 loads.
__global__ __launch_bounds__(256) void partial_kernel(int n)
{
    __shared__ float red_s[16][64];
    __shared__ float red_q[16][64];
    const int b = blockIdx.x, tdx = threadIdx.x;
    const int slot = tdx & 15;
    const int rgrp = tdx >> 4;       // 0..15
    const int r0 = b * TILE_V;

    float s0 = 0.f, s1 = 0.f, s2 = 0.f, s3 = 0.f;
    float q0 = 0.f, q1 = 0.f, q2 = 0.f, q3 = 0.f;
#pragma unroll
    for (int i = 0; i < 8; ++i) {
        const int r = r0 + rgrp + i * 16;
        if (r < n) {
            float4 x = ((const float4*)g_out_raw)[r * 16 + slot];
            s0 += x.x; s1 += x.y; s2 += x.z; s3 += x.w;
            q0 += x.x * x.x; q1 += x.y * x.y;
            q2 += x.z * x.z; q3 += x.w * x.w;
        }
    }
    red_s[rgrp][slot * 4 + 0] = s0;
    red_s[rgrp][slot * 4 + 1] = s1;
    red_s[rgrp][slot * 4 + 2] = s2;
    red_s[rgrp][slot * 4 + 3] = s3;
    red_q[rgrp][slot * 4 + 0] = q0;
    red_q[rgrp][slot * 4 + 1] = q1;
    red_q[rgrp][slot * 4 + 2] = q2;
    red_q[rgrp][slot * 4 + 3] = q3;
    __syncthreads();
    if (tdx < 64) {
        float ts = 0.f, tq = 0.f;
#pragma unroll
        for (int g = 0; g < 16; ++g) {
            ts += red_s[g][tdx];
            tq += red_q[g][tdx];
        }
        g_partial[(size_t)b * 128 + tdx]      = ts;
        g_partial[(size_t)b * 128 + 64 + tdx] = tq;
    }
}

// --------------------------- BN stats ---------------------------------------
__global__ __launch_bounds__(1024) void stats_kernel(
    const float* __restrict__ gamma, const float* __restrict__ beta,
    int n, int nblk)
{
    __shared__ float red[8][128];
    __shared__ double dd[128];
    const int t = threadIdx.x;
    const int c = t & 127;
    const int g = t >> 7;
    float a = 0.f;
    for (int b = g; b < nblk; b += 8)
        a += g_partial[(size_t)b * 128 + c];
    red[g][c] = a;
    __syncthreads();
    if (t < 128) {
        double tot = 0.0;
#pragma unroll
        for (int gg = 0; gg < 8; ++gg) tot += (double)red[gg][t];
        dd[t] = tot;
    }
    __syncthreads();
    if (t < 64) {
        const double mean = dd[t] / (double)n;
        const double var  = dd[64 + t] / (double)n - mean * mean;
        const double inv  = rsqrt(var + 1e-5);
        g_scale[t] = (float)((double)gamma[t] * inv);
        g_bias[t]  = (float)((double)beta[t] - mean * (double)gamma[t] * inv);
    }
}

// --------------------------- normalize + ReLU -------------------------------
__global__ __launch_bounds__(256) void bnrelu_kernel(float* __restrict__ out, int n)
{
    const int g = blockIdx.x * 256 + threadIdx.x;
    const int slot = g & 15;
    const int d0 = slot << 2;
    const float s0 = g_scale[d0],     s1 = g_scale[d0 + 1];
    const float s2 = g_scale[d0 + 2], s3 = g_scale[d0 + 3];
    const float b0 = g_bias[d0],      b1 = g_bias[d0 + 1];
    const float b2 = g_bias[d0 + 2],  b3 = g_bias[d0 + 3];
    const int rstride = (gridDim.x * 256) >> 4;
    for (int r = g >> 4; r < n; r += rstride) {
        const int i = r * 16 + slot;
        float4 x = ((const float4*)g_out_raw)[i];
        float4 y;
        y.x = fmaxf(fmaf(x.x, s0, b0), 0.f);
        y.y = fmaxf(fmaf(x.y, s1, b1), 0.f);
        y.z = fmaxf(fmaf(x.z, s2, b2), 0.f);
        y.w = fmaxf(fmaf(x.w, s3, b3), 0.f);
        ((float4*)out)[i] = y;
    }
}

// ---------------------------------------------------------------------------
extern "C" void kernel_launch(void* const* d_in, const int* in_sizes, int n_in,
                              void* d_out, int out_size)
{
    const float* feats  = (const float*)d_in[0];   // [N, 64]
    const float* weight = (const float*)d_in[1];   // [27, 64, 64]
    const float* gamma  = (const float*)d_in[2];   // [64]
    const float* beta   = (const float*)d_in[3];   // [64]
    const int*   nbr    = (const int*)d_in[4];     // [27, N]

    int n = in_sizes[0] / CIN;
    if (n > MAXN) n = MAXN;
    const int nblk = (n + TILE_V - 1) / TILE_V;

    static bool attr_set = false;
    if (!attr_set) {
        cudaFuncSetAttribute(center_kernel,
                             cudaFuncAttributeMaxDynamicSharedMemorySize, CT_SMEM);
        cudaFuncSetAttribute(sparse_kernel,
                             cudaFuncAttributeMaxDynamicSharedMemorySize, SP_SMEM);
        attr_set = true;
    }

    const int total4 = n * CIN / 4;
    const int nf_blocks = (total4 + 255) / 256;
    const int w_blocks  = (KVOL * CIN * COUT / 2 + 255) / 256;
    convert_kernel<<<nf_blocks + w_blocks, 256>>>(feats, weight, total4, nf_blocks);

    fill_kernel<<<KOFF * NCH, 256>>>(nbr, n);

    center_kernel<<<nblk, 128, CT_SMEM>>>(n);
    sparse_kernel<<<NSLOT, 128, SP_SMEM>>>(n);

    partial_kernel<<<nblk, 256>>>(n);
    stats_kernel<<<1, 1024>>>(gamma, beta, n, nblk);

    bnrelu_kernel<<<960, 256>>>((float*)d_out, n);
}

// round 16
// speedup vs baseline: 1.1692x; 1.0287x over previous
#include <cuda_runtime.h>
#include <cuda_fp16.h>
#include <cstdint>

#define CIN    64
#define COUT   64
#define KVOL   27
#define TILE_V 128
#define MAXN   120000
#define NBLK   ((MAXN + TILE_V - 1) / TILE_V)   // 938
#define NROWS  (NBLK * TILE_V)                   // 120064 padded rows
#define KOFF   26
#define PAIRCAP 8192
#define CHSZ   2048
#define NCH    ((MAXN + CHSZ - 1) / CHSZ)       // 59
#define STILE  64
#define NSLOT  (KOFF * STILE)                    // 1664

// padded A row: 144 B (72 halves); 144 mod 128 = 16 -> conflict-free ldmatrix
#define ROWB   144
#define ROWH   72

// sparse smem: A @0 (18432), W @18432 (8192), dlist @26624 (512), mbar @27136
#define SP_W    18432
#define SP_DL   26624
#define SP_MB   27136
#define SP_SMEM 27200
// center smem: A @0 (18432), W @18432 (8192), mbar @26624
#define CT_MB   26624
#define CT_SMEM 26688

// ---- device scratch (allocation-free; zero-initialized at module load) ----
__device__ __align__(16) float  g_out_raw[(size_t)MAXN * COUT];
__device__ __align__(16) __half g_fhp[(size_t)NROWS * ROWH];     // padded rows
__device__ __align__(16) __half g_whs[KVOL * CIN * COUT];        // pre-swizzled
__device__ __align__(16) __half g_zero[64];                      // zero row
__device__ int   g_psrc[KOFF * PAIRCAP];
__device__ int   g_pdst[KOFF * PAIRCAP];
__device__ int   g_mcount[KOFF];    // reset at END of bnrelu for the next call
__device__ float g_partial[(size_t)NBLK * 2 * COUT];
__device__ float g_scale[COUT];
__device__ float g_bias[COUT];

// --------------------------- PTX helpers -----------------------------------
__device__ __forceinline__ uint32_t smem_u32(const void* p) {
    return (uint32_t)__cvta_generic_to_shared(p);
}
__device__ __forceinline__ void bulkcp(uint32_t dst, const void* src,
                                       uint32_t bytes, uint32_t mbar) {
    asm volatile("cp.async.bulk.shared::cta.global.mbarrier::complete_tx::bytes "
                 "[%0], [%1], %2, [%3];"
                 :: "r"(dst), "l"(src), "r"(bytes), "r"(mbar) : "memory");
}
__device__ __forceinline__ void mbar_init(uint32_t a, uint32_t cnt) {
    asm volatile("mbarrier.init.shared.b64 [%0], %1;" :: "r"(a), "r"(cnt) : "memory");
}
__device__ __forceinline__ void mbar_expect(uint32_t a, uint32_t bytes) {
    asm volatile("mbarrier.arrive.expect_tx.shared.b64 _, [%0], %1;"
                 :: "r"(a), "r"(bytes) : "memory");
}
__device__ __forceinline__ void mbar_wait(uint32_t a, uint32_t parity) {
    uint32_t done;
    asm volatile("{\n\t.reg .pred p;\n\t"
                 "mbarrier.try_wait.parity.acquire.cta.shared::cta.b64 p, [%1], %2;\n\t"
                 "selp.b32 %0, 1, 0, p;\n\t}"
                 : "=r"(done) : "r"(a), "r"(parity) : "memory");
    if (!done) {
        asm volatile("{\n\t.reg .pred P1;\n\t"
                     "WL_%=:\n\t"
                     "mbarrier.try_wait.parity.acquire.cta.shared::cta.b64 P1, [%0], %1, 0x989680;\n\t"
                     "@P1 bra.uni WD_%=;\n\t"
                     "bra.uni WL_%=;\n\t"
                     "WD_%=:\n\t}" :: "r"(a), "r"(parity) : "memory");
    }
}
__device__ __forceinline__ void ldmx4(uint32_t& r0, uint32_t& r1, uint32_t& r2,
                                      uint32_t& r3, uint32_t a) {
    asm volatile("ldmatrix.sync.aligned.m8n8.x4.shared.b16 {%0,%1,%2,%3}, [%4];"
                 : "=r"(r0), "=r"(r1), "=r"(r2), "=r"(r3) : "r"(a));
}
__device__ __forceinline__ void ldmx4t(uint32_t& r0, uint32_t& r1, uint32_t& r2,
                                       uint32_t& r3, uint32_t a) {
    asm volatile("ldmatrix.sync.aligned.m8n8.x4.trans.shared.b16 {%0,%1,%2,%3}, [%4];"
                 : "=r"(r0), "=r"(r1), "=r"(r2), "=r"(r3) : "r"(a));
}
__device__ __forceinline__ void mma16816(float* c, const uint32_t* a,
                                         const uint32_t* b) {
    asm volatile(
        "mma.sync.aligned.m16n8k16.row.col.f32.f16.f16.f32 "
        "{%0,%1,%2,%3}, {%4,%5,%6,%7}, {%8,%9}, {%0,%1,%2,%3};"
        : "+f"(c[0]), "+f"(c[1]), "+f"(c[2]), "+f"(c[3])
        : "r"(a[0]), "r"(a[1]), "r"(a[2]), "r"(a[3]), "r"(b[0]), "r"(b[1]));
}
__device__ __forceinline__ void redadd4(float* p, float a, float b,
                                        float c, float d) {
    asm volatile("red.global.add.v4.f32 [%0], {%1, %2, %3, %4};"
                 :: "l"(p), "f"(a), "f"(b), "f"(c), "f"(d) : "memory");
}

// --------------------------- merged prologue --------------------------------
// sections: [0,nf): feats->padded fp16; [nf,nf+w): weight->swizzle;
// [nf+w, nf+w+fillb): pair-list compaction (independent of converts).
// g_mcount was reset by the tail of the previous launch sequence (or is
// zero-initialized on first call).
__global__ __launch_bounds__(256) void prologue_kernel(
    const float* __restrict__ feats, const float* __restrict__ weight,
    const int* __restrict__ nbr,
    int n, int total4, int nf_blocks, int w_blocks)
{
    const int bid = blockIdx.x;
    if (bid < nf_blocks) {
        int idx = bid * 256 + threadIdx.x;
        if (idx >= total4) return;
        float4 x = ((const float4*)feats)[idx];
        const int row = idx >> 4, c4 = idx & 15;
        __half2* ph = (__half2*)g_fhp;
        const size_t o = (size_t)row * (ROWH / 2) + c4 * 2;
        ph[o]     = __floats2half2_rn(x.x, x.y);
        ph[o + 1] = __floats2half2_rn(x.z, x.w);
        return;
    }
    if (bid < nf_blocks + w_blocks) {
        int idx = (bid - nf_blocks) * 256 + threadIdx.x;   // half2 index
        if (idx * 2 >= KVOL * CIN * COUT) return;
        float2 w = ((const float2*)weight)[idx];
        const int k = idx / 2048, i = idx % 2048;
        const int b = i * 4;
        const int r = b >> 7, c = (b >> 4) & 7, rem = b & 15;
        const int swz = r * 128 + ((c ^ (r & 7)) << 4) + rem;
        ((__half2*)g_whs)[(k * 8192 + swz) >> 2] = __floats2half2_rn(w.x, w.y);
        return;
    }
    // ---- fill section: warp-autonomous pair compaction ----
    const int fb = bid - nf_blocks - w_blocks;   // 0 .. KOFF*NCH-1
    const int kk = fb / NCH;
    const int ch = fb % NCH;
    const int k  = (kk < 13) ? kk : kk + 1;
    const int tid  = threadIdx.x;
    const int lane = tid & 31;
    const int idx0 = ch * CHSZ + tid * 8;

    int v[8];
    if (idx0 + 7 < n) {
        const int4* p = (const int4*)(nbr + (size_t)k * n + idx0);
        int4 x0 = __ldg(p);
        int4 x1 = __ldg(p + 1);
        v[0] = x0.x; v[1] = x0.y; v[2] = x0.z; v[3] = x0.w;
        v[4] = x1.x; v[5] = x1.y; v[6] = x1.z; v[7] = x1.w;
    } else {
#pragma unroll
        for (int j = 0; j < 8; ++j) {
            const int idx = idx0 + j;
            v[j] = (idx < n) ? __ldg(nbr + (size_t)k * n + idx) : -1;
        }
    }
    int tc = 0;
#pragma unroll
    for (int j = 0; j < 8; ++j)
        if (v[j] >= 0) ++tc;

    int sc = tc;
#pragma unroll
    for (int off = 1; off < 32; off <<= 1) {
        int t = __shfl_up_sync(0xFFFFFFFFu, sc, off);
        if (lane >= off) sc += t;
    }
    int wb = 0;
    if (lane == 31) wb = atomicAdd(&g_mcount[kk], sc);
    wb = __shfl_sync(0xFFFFFFFFu, wb, 31);

    int pos = wb + sc - tc;
#pragma unroll
    for (int j = 0; j < 8; ++j) {
        if (v[j] >= 0) {
            if (pos < PAIRCAP) {
                g_psrc[kk * PAIRCAP + pos] = v[j];
                g_pdst[kk * PAIRCAP + pos] = idx0 + j;
            }
            ++pos;
        }
    }
}

// --------------------------- center GEMM (k=13, dense write) ----------------
__global__ __launch_bounds__(128) void center_kernel(int n)
{
    extern __shared__ char smem[];
    const uint32_t sb = smem_u32(smem);
    const int tid  = threadIdx.x;
    const int wid  = tid >> 5;
    const int lane = tid & 31;
    const int warp_m = wid >> 1;
    const int warp_n = wid & 1;
    const int v0 = blockIdx.x * TILE_V;

    const int l15   = lane & 15;
    const int lhalf = lane >> 4;

    if (tid == 0) mbar_init(sb + CT_MB, 1);
    __syncthreads();
    if (tid == 0) {
        mbar_expect(sb + CT_MB, 18432 + 8192);
        bulkcp(sb, g_fhp + (size_t)v0 * ROWH, 18432, sb + CT_MB);
        bulkcp(sb + SP_W, g_whs + 13 * 4096, 8192, sb + CT_MB);
    }
    mbar_wait(sb + CT_MB, 0);

    float acc[4][4][4];
#pragma unroll
    for (int mi = 0; mi < 4; ++mi)
#pragma unroll
        for (int ni = 0; ni < 4; ++ni)
#pragma unroll
            for (int r = 0; r < 4; ++r) acc[mi][ni][r] = 0.f;

    const uint32_t arow = (uint32_t)(warp_m * 64 + l15);
    const uint32_t bkrow = (uint32_t)l15;
    const uint32_t bxor  = (uint32_t)(l15 & 7);

#pragma unroll
    for (int ks = 0; ks < 4; ++ks) {
        uint32_t bfrag[4][2];
#pragma unroll
        for (int p = 0; p < 2; ++p) {
            const uint32_t kk2 = bkrow + ks * 16;
            const uint32_t ch = (uint32_t)(warp_n * 4 + 2 * p + lhalf);
            const uint32_t ad = sb + SP_W + kk2 * 128 + ((ch ^ bxor) << 4);
            ldmx4t(bfrag[2 * p][0], bfrag[2 * p][1],
                   bfrag[2 * p + 1][0], bfrag[2 * p + 1][1], ad);
        }
#pragma unroll
        for (int mi = 0; mi < 4; ++mi) {
            const uint32_t row = arow + mi * 16;
            const uint32_t ch  = (uint32_t)(ks * 2 + lhalf);
            const uint32_t ad  = sb + row * ROWB + (ch << 4);
            uint32_t afrag[4];
            ldmx4(afrag[0], afrag[1], afrag[2], afrag[3], ad);
#pragma unroll
            for (int ni = 0; ni < 4; ++ni)
                mma16816(acc[mi][ni], afrag, bfrag[ni]);
        }
    }

    const int rbase = v0 + warp_m * 64 + (lane >> 2);
    const int cbase = warp_n * 32 + (lane & 3) * 2;
#pragma unroll
    for (int mi = 0; mi < 4; ++mi) {
#pragma unroll
        for (int ni = 0; ni < 4; ++ni) {
            const int r0 = rbase + mi * 16;
            const int cc = cbase + ni * 8;
            if (r0 < n)
                *(float2*)(g_out_raw + (size_t)r0 * COUT + cc) =
                    make_float2(acc[mi][ni][0], acc[mi][ni][1]);
            if (r0 + 8 < n)
                *(float2*)(g_out_raw + (size_t)(r0 + 8) * COUT + cc) =
                    make_float2(acc[mi][ni][2], acc[mi][ni][3]);
        }
    }
}

// --------------------------- sparse GEMM + v4 scatter ------------------------
__global__ __launch_bounds__(128) void sparse_kernel(int n)
{
    const int kk = blockIdx.x / STILE;
    const int t  = blockIdx.x % STILE;
    int Mk = __ldg(&g_mcount[kk]);
    if (Mk > PAIRCAP) Mk = PAIRCAP;
    const int m0 = t * TILE_V;
    if (m0 >= Mk) return;

    extern __shared__ char smem[];
    const uint32_t sb = smem_u32(smem);
    const int* dlist = (const int*)(smem + SP_DL);
    const int tid  = threadIdx.x;
    const int wid  = tid >> 5;
    const int lane = tid & 31;
    const int warp_m = wid >> 1;
    const int warp_n = wid & 1;

    const int l15   = lane & 15;
    const int lhalf = lane >> 4;

    if (tid == 0) mbar_init(sb + SP_MB, 1);
    __syncthreads();
    if (tid == 0)
        mbar_expect(sb + SP_MB, 16384 + 8192 + 512);

    {
        const bool valid = (m0 + tid) < Mk;
        const int src = valid ? __ldg(g_psrc + kk * PAIRCAP + m0 + tid) : 0;
        const __half* sp = valid ? (g_fhp + (size_t)src * ROWH) : g_zero;
        bulkcp(sb + (uint32_t)tid * ROWB, sp, 128, sb + SP_MB);
    }
    if (tid == 0) {
        const int k = (kk < 13) ? kk : kk + 1;
        bulkcp(sb + SP_W, g_whs + k * 4096, 8192, sb + SP_MB);
        bulkcp(sb + SP_DL, g_pdst + kk * PAIRCAP + m0, 512, sb + SP_MB);
    }
    mbar_wait(sb + SP_MB, 0);

    float acc[4][4][4];
#pragma unroll
    for (int mi = 0; mi < 4; ++mi)
#pragma unroll
        for (int ni = 0; ni < 4; ++ni)
#pragma unroll
            for (int r = 0; r < 4; ++r) acc[mi][ni][r] = 0.f;

    const uint32_t arow = (uint32_t)(warp_m * 64 + l15);
    const uint32_t bkrow = (uint32_t)l15;
    const uint32_t bxor  = (uint32_t)(l15 & 7);

#pragma unroll
    for (int ks = 0; ks < 4; ++ks) {
        uint32_t bfrag[4][2];
#pragma unroll
        for (int p = 0; p < 2; ++p) {
            const uint32_t kk2 = bkrow + ks * 16;
            const uint32_t ch = (uint32_t)(warp_n * 4 + 2 * p + lhalf);
            const uint32_t ad = sb + SP_W + kk2 * 128 + ((ch ^ bxor) << 4);
            ldmx4t(bfrag[2 * p][0], bfrag[2 * p][1],
                   bfrag[2 * p + 1][0], bfrag[2 * p + 1][1], ad);
        }
#pragma unroll
        for (int mi = 0; mi < 4; ++mi) {
            const uint32_t row = arow + mi * 16;
            const uint32_t ch  = (uint32_t)(ks * 2 + lhalf);
            const uint32_t ad  = sb + row * ROWB + (ch << 4);
            uint32_t afrag[4];
            ldmx4(afrag[0], afrag[1], afrag[2], afrag[3], ad);
#pragma unroll
            for (int ni = 0; ni < 4; ++ni)
                mma16816(acc[mi][ni], afrag, bfrag[ni]);
        }
    }

    const int rloc = warp_m * 64 + (lane >> 2);
    const int cq = warp_n * 32 + (lane & 3) * 2;
#pragma unroll
    for (int mi = 0; mi < 4; ++mi) {
        const int r0 = rloc + mi * 16;
        const int r1 = r0 + 8;
        const int d0 = (m0 + r0 < Mk) ? dlist[r0] : -1;
        const int d1 = (m0 + r1 < Mk) ? dlist[r1] : -1;
#pragma unroll
        for (int ni = 0; ni < 4; ++ni) {
            float a0 = acc[mi][ni][0], a1 = acc[mi][ni][1];
            float a2 = acc[mi][ni][2], a3 = acc[mi][ni][3];
            float p0 = __shfl_xor_sync(0xFFFFFFFFu, a0, 1);
            float p1 = __shfl_xor_sync(0xFFFFFFFFu, a1, 1);
            float p2 = __shfl_xor_sync(0xFFFFFFFFu, a2, 1);
            float p3 = __shfl_xor_sync(0xFFFFFFFFu, a3, 1);
            if (!(lane & 1)) {
                const int cc = cq + ni * 8;
                if (d0 >= 0)
                    redadd4(g_out_raw + (size_t)d0 * COUT + cc, a0, a1, p0, p1);
                if (d1 >= 0)
                    redadd4(g_out_raw + (size_t)d1 * COUT + cc, a2, a3, p2, p3);
            }
        }
    }
}

// --------------------------- BN partials (coalesced float4) ------------------
__global__ __launch_bounds__(256) void partial_kernel(int n)
{
    __shared__ float red_s[16][64];
    __shared__ float red_q[16][64];
    const int b = blockIdx.x, tdx = threadIdx.x;
    const int slot = tdx & 15;
    const int rgrp = tdx >> 4;       // 0..15
    const int r0 = b * TILE_V;

    float s0 = 0.f, s1 = 0.f, s2 = 0.f, s3 = 0.f;
    float q0 = 0.f, q1 = 0.f, q2 = 0.f, q3 = 0.f;
#pragma unroll
    for (int i = 0; i < 8; ++i) {
        const int r = r0 + rgrp + i * 16;
        if (r < n) {
            float4 x = ((const float4*)g_out_raw)[r * 16 + slot];
            s0 += x.x; s1 += x.y; s2 += x.z; s3 += x.w;
            q0 += x.x * x.x; q1 += x.y * x.y;
            q2 += x.z * x.z; q3 += x.w * x.w;
        }
    }
    red_s[rgrp][slot * 4 + 0] = s0;
    red_s[rgrp][slot * 4 + 1] = s1;
    red_s[rgrp][slot * 4 + 2] = s2;
    red_s[rgrp][slot * 4 + 3] = s3;
    red_q[rgrp][slot * 4 + 0] = q0;
    red_q[rgrp][slot * 4 + 1] = q1;
    red_q[rgrp][slot * 4 + 2] = q2;
    red_q[rgrp][slot * 4 + 3] = q3;
    __syncthreads();
    if (tdx < 64) {
        float ts = 0.f, tq = 0.f;
#pragma unroll
        for (int g = 0; g < 16; ++g) {
            ts += red_s[g][tdx];
            tq += red_q[g][tdx];
        }
        g_partial[(size_t)b * 128 + tdx]      = ts;
        g_partial[(size_t)b * 128 + 64 + tdx] = tq;
    }
}

// --------------------------- BN stats ---------------------------------------
__global__ __launch_bounds__(1024) void stats_kernel(
    const float* __restrict__ gamma, const float* __restrict__ beta,
    int n, int nblk)
{
    __shared__ float red[8][128];
    __shared__ double dd[128];
    const int t = threadIdx.x;
    const int c = t & 127;
    const int g = t >> 7;
    float a = 0.f;
    for (int b = g; b < nblk; b += 8)
        a += g_partial[(size_t)b * 128 + c];
    red[g][c] = a;
    __syncthreads();
    if (t < 128) {
        double tot = 0.0;
#pragma unroll
        for (int gg = 0; gg < 8; ++gg) tot += (double)red[gg][t];
        dd[t] = tot;
    }
    __syncthreads();
    if (t < 64) {
        const double mean = dd[t] / (double)n;
        const double var  = dd[64 + t] / (double)n - mean * mean;
        const double inv  = rsqrt(var + 1e-5);
        g_scale[t] = (float)((double)gamma[t] * inv);
        g_bias[t]  = (float)((double)beta[t] - mean * (double)gamma[t] * inv);
    }
}

// --------------------------- normalize + ReLU + counter reset ----------------
__global__ __launch_bounds__(256) void bnrelu_kernel(float* __restrict__ out, int n)
{
    // reset pair counters for the NEXT kernel_launch call / graph replay
    if (blockIdx.x == 0 && threadIdx.x < KOFF) g_mcount[threadIdx.x] = 0;

    const int g = blockIdx.x * 256 + threadIdx.x;
    const int slot = g & 15;
    const int d0 = slot << 2;
    const float s0 = g_scale[d0],     s1 = g_scale[d0 + 1];
    const float s2 = g_scale[d0 + 2], s3 = g_scale[d0 + 3];
    const float b0 = g_bias[d0],      b1 = g_bias[d0 + 1];
    const float b2 = g_bias[d0 + 2],  b3 = g_bias[d0 + 3];
    const int rstride = (gridDim.x * 256) >> 4;
    for (int r = g >> 4; r < n; r += rstride) {
        const int i = r * 16 + slot;
        float4 x = ((const float4*)g_out_raw)[i];
        float4 y;
        y.x = fmaxf(fmaf(x.x, s0, b0), 0.f);
        y.y = fmaxf(fmaf(x.y, s1, b1), 0.f);
        y.z = fmaxf(fmaf(x.z, s2, b2), 0.f);
        y.w = fmaxf(fmaf(x.w, s3, b3), 0.f);
        ((float4*)out)[i] = y;
    }
}

// ---------------------------------------------------------------------------
extern "C" void kernel_launch(void* const* d_in, const int* in_sizes, int n_in,
                              void* d_out, int out_size)
{
    const float* feats  = (const float*)d_in[0];   // [N, 64]
    const float* weight = (const float*)d_in[1];   // [27, 64, 64]
    const float* gamma  = (const float*)d_in[2];   // [64]
    const float* beta   = (const float*)d_in[3];   // [64]
    const int*   nbr    = (const int*)d_in[4];     // [27, N]

    int n = in_sizes[0] / CIN;
    if (n > MAXN) n = MAXN;
    const int nblk = (n + TILE_V - 1) / TILE_V;

    static bool attr_set = false;
    if (!attr_set) {
        cudaFuncSetAttribute(center_kernel,
                             cudaFuncAttributeMaxDynamicSharedMemorySize, CT_SMEM);
        cudaFuncSetAttribute(sparse_kernel,
                             cudaFuncAttributeMaxDynamicSharedMemorySize, SP_SMEM);
        attr_set = true;
    }

    const int total4 = n * CIN / 4;
    const int nf_blocks = (total4 + 255) / 256;
    const int w_blocks  = (KVOL * CIN * COUT / 2 + 255) / 256;
    const int f_blocks  = KOFF * NCH;
    prologue_kernel<<<nf_blocks + w_blocks + f_blocks, 256>>>(
        feats, weight, nbr, n, total4, nf_blocks, w_blocks);

    center_kernel<<<nblk, 128, CT_SMEM>>>(n);
    sparse_kernel<<<NSLOT, 128, SP_SMEM>>>(n);

    partial_kernel<<<nblk, 256>>>(n);
    stats_kernel<<<1, 1024>>>(gamma, beta, n, nblk);

    bnrelu_kernel<<<960, 256>>>((float*)d_out, n);
}